// round 11
// baseline (speedup 1.0000x reference)
#include <cuda_runtime.h>
#include <cuda_bf16.h>
#include <stdint.h>

// ---------------------------------------------------------------------------
// out = relu(relu(conv3x3(x) @ w1 + b1) @ w2 + b2) @ w3 + b3 , B=65536
// conv folded into FC1 (W_eff). GEMMs via mma.sync m16n8k16 bf16 with hi/lo
// x3 split (ah*bh + al*bh + ah*bl). This round: cp.async double-buffered B,
// register-prefetched A, ldmatrix.x4 B fragments, chunk-major weight images.
// ---------------------------------------------------------------------------

#define CTA_M    128
#define NTHREADS 512

// prep scratch: weight images in EXACT smem layout (chunk-major, 72-elem rows)
__device__ __align__(16) __nv_bfloat16 g_w1hi[13 * 256 * 72];
__device__ __align__(16) __nv_bfloat16 g_w1lo[13 * 256 * 72];
__device__ __align__(16) __nv_bfloat16 g_w2hi[4 * 128 * 72];
__device__ __align__(16) __nv_bfloat16 g_w2lo[4 * 128 * 72];

// ---- smem layout (bytes, dynamic) ----
#define SM_B1   0                    // 256 f32
#define SM_B2   1024                 // 128 f32
#define SM_B3   1536                 // 16 f32
#define SM_W3   1600                 // 1280 f32
#define SM_MAIN 6720
// layer-1 phase: A single buffer, B double buffer
#define L1A_HI  (SM_MAIN)            // [128][72] bf16, stride 144 B
#define L1A_LO  (SM_MAIN + 18432)
#define L1B(b)  (SM_MAIN + 36864 + (b) * 73728)   // hi +0, lo +36864
// layer-2 phase (overlays dead L1 buffers)
#define H1_HI   (SM_MAIN)            // 4 chunks x [128][72], chunk-major
#define H1_LO   (SM_MAIN + 73728)
#define L2B(b)  (SM_MAIN + 147456 + (b) * 36864)  // hi +0, lo +18432
// layer-3 phase
#define H2_F32  (SM_MAIN)            // [128][132] f32
#define SMEM_SZ 227904

// ---------------------------------------------------------------------------
__device__ __forceinline__ uint32_t s2u(const void* p) {
    uint32_t a;
    asm("{ .reg .u64 t; cvta.to.shared.u64 t, %1; cvt.u32.u64 %0, t; }"
        : "=r"(a) : "l"(p));
    return a;
}
__device__ __forceinline__ void ldmx4(uint32_t* r, uint32_t addr) {
    asm volatile("ldmatrix.sync.aligned.m8n8.x4.shared.b16 {%0,%1,%2,%3}, [%4];"
                 : "=r"(r[0]), "=r"(r[1]), "=r"(r[2]), "=r"(r[3]) : "r"(addr));
}
__device__ __forceinline__ void mma16816(float* c, const uint32_t* a,
                                         const uint32_t* b) {
    asm volatile(
        "mma.sync.aligned.m16n8k16.row.col.f32.bf16.bf16.f32 "
        "{%0,%1,%2,%3}, {%4,%5,%6,%7}, {%8,%9}, {%0,%1,%2,%3};"
        : "+f"(c[0]), "+f"(c[1]), "+f"(c[2]), "+f"(c[3])
        : "r"(a[0]), "r"(a[1]), "r"(a[2]), "r"(a[3]), "r"(b[0]), "r"(b[1]));
}
#define CP16(dst, src) \
    asm volatile("cp.async.cg.shared.global [%0], [%1], 16;" \
                 :: "r"(dst), "l"(src) : "memory")
#define CP_COMMIT() asm volatile("cp.async.commit_group;" ::: "memory")
#define CP_WAIT0()  asm volatile("cp.async.wait_group 0;" ::: "memory")

__device__ __forceinline__ uint32_t pk(__nv_bfloat16 a, __nv_bfloat16 b) {
    unsigned short ra = *(unsigned short*)&a, rb = *(unsigned short*)&b;
    return (uint32_t)ra | ((uint32_t)rb << 16);
}
__device__ __forceinline__ void split2(float v0, float v1,
                                       uint32_t& hi, uint32_t& lo) {
    __nv_bfloat16 h0 = __float2bfloat16(v0);
    __nv_bfloat16 h1 = __float2bfloat16(v1);
    __nv_bfloat16 l0 = __float2bfloat16(v0 - __bfloat162float(h0));
    __nv_bfloat16 l1 = __float2bfloat16(v1 - __bfloat162float(h1));
    hi = pk(h0, h1);
    lo = pk(l0, l1);
}

// ---------------------------------------------------------------------------
// prep kernels: emit weight images chunk-major with 72-elem padded rows
// ---------------------------------------------------------------------------
__global__ void prep_w1T(const float* __restrict__ cw,
                         const float* __restrict__ w1) {
    int idx = blockIdx.x * 256 + threadIdx.x;   // 256*832
    int n = idx / 832, p = idx % 832;
    float acc = 0.f;
    if (p < 784) {
        int r = p / 28, c = p % 28;
#pragma unroll
        for (int dr = 0; dr < 3; dr++)
#pragma unroll
            for (int dc = 0; dc < 3; dc++) {
                int rr = r - dr, cc = c - dc;
                if (rr >= 0 && rr < 26 && cc >= 0 && cc < 26)
                    acc += cw[dr * 3 + dc] * w1[(rr * 26 + cc) * 256 + n];
            }
    }
    __nv_bfloat16 h = __float2bfloat16(acc);
    __nv_bfloat16 l = __float2bfloat16(acc - __bfloat162float(h));
    int cc = p >> 6, kin = p & 63;
    int off = cc * 18432 + n * 72 + kin;
    g_w1hi[off] = h;
    g_w1lo[off] = l;
}

__global__ void prep_w2T(const float* __restrict__ w2) {
    int idx = blockIdx.x * 256 + threadIdx.x;   // 128*256
    int n = idx / 256, k = idx % 256;
    float v = w2[k * 128 + n];
    __nv_bfloat16 h = __float2bfloat16(v);
    __nv_bfloat16 l = __float2bfloat16(v - __bfloat162float(h));
    int ch = k >> 6, kin = k & 63;
    int off = ch * 9216 + n * 72 + kin;
    g_w2hi[off] = h;
    g_w2lo[off] = l;
}

// ---------------------------------------------------------------------------
// fused MLP: 1 CTA = 128 batch rows, 512 threads = 16 warps (4x4 warp grid)
// ---------------------------------------------------------------------------
__global__ void __launch_bounds__(NTHREADS, 1)
fused_mlp(const float* __restrict__ x, const float* __restrict__ b1g,
          const float* __restrict__ b2g, const float* __restrict__ b3g,
          const float* __restrict__ w3g, float* __restrict__ out) {
    extern __shared__ unsigned char smem[];
    const uint32_t sb = s2u(smem);
    const int tid = threadIdx.x;
    const int lane = tid & 31;
    const int wid = tid >> 5;
    const int wm = wid >> 2;
    const int wn = wid & 3;
    const int g = lane >> 2;
    const int t4 = lane & 3;

    float* b1s = (float*)(smem + SM_B1);
    float* b2s = (float*)(smem + SM_B2);
    float* b3s = (float*)(smem + SM_B3);
    float* w3s = (float*)(smem + SM_W3);
    for (int i = tid; i < 256; i += NTHREADS) b1s[i] = b1g[i];
    if (tid < 128) b2s[tid] = b2g[tid];
    if (tid < 16)  b3s[tid] = (tid < 10) ? b3g[tid] : 0.f;
    for (int i = tid; i < 1280; i += NTHREADS) w3s[i] = w3g[i];

    const float* xblk = x + (size_t)blockIdx.x * CTA_M * 784;

    // ---------------- layer 1: [128,832] x [832,256] -----------------------
    float c1[2][8][4];
#pragma unroll
    for (int a = 0; a < 2; a++)
#pragma unroll
        for (int b = 0; b < 8; b++)
#pragma unroll
            for (int c = 0; c < 4; c++) c1[a][b][c] = 0.f;

    // prologue: B chunk 0 via cp.async; A chunk 0 into regs
    {
        uint32_t dst = sb + L1B(0);
        const uint4* sh = (const uint4*)g_w1hi;
        const uint4* sl = (const uint4*)g_w1lo;
        for (int i = tid; i < 2304; i += NTHREADS) {
            CP16(dst + i * 16, sh + i);
            CP16(dst + 36864 + i * 16, sl + i);
        }
        CP_COMMIT();
    }
    float4 r[4];
#pragma unroll
    for (int j = 0; j < 4; j++) {
        int idx = tid + NTHREADS * j;
        int row = idx >> 4, f4 = idx & 15;
        r[j] = *(const float4*)(xblk + (size_t)row * 784 + f4 * 4);
    }

    for (int cc = 0; cc < 13; cc++) {
        CP_WAIT0();
        __syncthreads();   // B(cc) visible; MMA cc-1 fully done

        // issue B(cc+1) — overlaps the STS + MMA below
        if (cc < 12) {
            uint32_t dst = sb + L1B((cc + 1) & 1);
            const uint4* sh = (const uint4*)g_w1hi + (cc + 1) * 2304;
            const uint4* sl = (const uint4*)g_w1lo + (cc + 1) * 2304;
            for (int i = tid; i < 2304; i += NTHREADS) {
                CP16(dst + i * 16, sh + i);
                CP16(dst + 36864 + i * 16, sl + i);
            }
            CP_COMMIT();
        }
        // STS A(cc) from prefetched regs (single A buffer — safe after sync)
#pragma unroll
        for (int j = 0; j < 4; j++) {
            int idx = tid + NTHREADS * j;
            int row = idx >> 4, f4 = idx & 15;
            uint32_t h0, l0, h1, l1;
            split2(r[j].x, r[j].y, h0, l0);
            split2(r[j].z, r[j].w, h1, l1);
            uint32_t off = row * 144 + f4 * 8;
            *(uint2*)(smem + L1A_HI + off) = make_uint2(h0, h1);
            *(uint2*)(smem + L1A_LO + off) = make_uint2(l0, l1);
        }
        // prefetch A(cc+1) — latency hidden by MMA(cc)
        if (cc < 12) {
            int nc = cc + 1;
#pragma unroll
            for (int j = 0; j < 4; j++) {
                int idx = tid + NTHREADS * j;
                int row = idx >> 4, f4 = idx & 15;
                r[j] = make_float4(0.f, 0.f, 0.f, 0.f);
                if (nc < 12 || f4 < 4)
                    r[j] = *(const float4*)(xblk + (size_t)row * 784 + nc * 64 + f4 * 4);
            }
        }
        __syncthreads();   // A(cc) visible

        // MMA chunk cc
        const uint32_t bbase = sb + L1B(cc & 1);
#pragma unroll
        for (int ks = 0; ks < 4; ks++) {
            uint32_t ah[2][4], al[2][4];
#pragma unroll
            for (int mf = 0; mf < 2; mf++) {
                uint32_t aa = sb + L1A_HI +
                    (32 * wm + 16 * mf + (lane & 15)) * 144 +
                    ks * 32 + ((lane >> 4) << 4);
                ldmx4(ah[mf], aa);
                ldmx4(al[mf], aa + 18432);
            }
#pragma unroll
            for (int jj = 0; jj < 4; jj++) {
                uint32_t ba = bbase +
                    (64 * wn + 16 * jj + (lane & 7) + ((lane >> 4) << 3)) * 144 +
                    ks * 32 + (((lane >> 3) & 1) << 4);
                uint32_t bh[4], bl[4];
                ldmx4(bh, ba);
                ldmx4(bl, ba + 36864);
#pragma unroll
                for (int mf = 0; mf < 2; mf++) {
                    mma16816(c1[mf][2 * jj],     ah[mf], bh);
                    mma16816(c1[mf][2 * jj],     al[mf], bh);
                    mma16816(c1[mf][2 * jj],     ah[mf], bl);
                    mma16816(c1[mf][2 * jj + 1], ah[mf], bh + 2);
                    mma16816(c1[mf][2 * jj + 1], al[mf], bh + 2);
                    mma16816(c1[mf][2 * jj + 1], ah[mf], bl + 2);
                }
            }
        }
    }

    // L1 epilogue: h1 = relu(c1+b1) -> H1 chunk-major bf16 hi/lo
    __syncthreads();
#pragma unroll
    for (int mf = 0; mf < 2; mf++)
#pragma unroll
        for (int j = 0; j < 8; j++)
#pragma unroll
            for (int ci = 0; ci < 4; ci += 2) {
                int row = 32 * wm + 16 * mf + g + (ci ? 8 : 0);
                int col = 64 * wn + 8 * j + 2 * t4;
                float v0 = fmaxf(c1[mf][j][ci]     + b1s[col],     0.f);
                float v1 = fmaxf(c1[mf][j][ci + 1] + b1s[col + 1], 0.f);
                uint32_t hi, lo;
                split2(v0, v1, hi, lo);
                uint32_t off = wn * 18432 + row * 144 + (8 * j + 2 * t4) * 2;
                *(uint32_t*)(smem + H1_HI + off) = hi;
                *(uint32_t*)(smem + H1_LO + off) = lo;
            }
    // issue w2 B chunk 0 (region disjoint from H1)
    {
        uint32_t dst = sb + L2B(0);
        const uint4* sh = (const uint4*)g_w2hi;
        const uint4* sl = (const uint4*)g_w2lo;
        for (int i = tid; i < 1152; i += NTHREADS) {
            CP16(dst + i * 16, sh + i);
            CP16(dst + 18432 + i * 16, sl + i);
        }
        CP_COMMIT();
    }

    // ---------------- layer 2: [128,256] x [256,128] -----------------------
    float c2[2][4][4];
#pragma unroll
    for (int a = 0; a < 2; a++)
#pragma unroll
        for (int b = 0; b < 4; b++)
#pragma unroll
            for (int c = 0; c < 4; c++) c2[a][b][c] = 0.f;

    for (int ch = 0; ch < 4; ch++) {
        CP_WAIT0();
        __syncthreads();
        if (ch < 3) {
            uint32_t dst = sb + L2B((ch + 1) & 1);
            const uint4* sh = (const uint4*)g_w2hi + (ch + 1) * 1152;
            const uint4* sl = (const uint4*)g_w2lo + (ch + 1) * 1152;
            for (int i = tid; i < 1152; i += NTHREADS) {
                CP16(dst + i * 16, sh + i);
                CP16(dst + 18432 + i * 16, sl + i);
            }
            CP_COMMIT();
        }
        const uint32_t bbase = sb + L2B(ch & 1);
        const uint32_t abase = sb + H1_HI + ch * 18432;
#pragma unroll
        for (int ks = 0; ks < 4; ks++) {
            uint32_t ah[2][4], al[2][4];
#pragma unroll
            for (int mf = 0; mf < 2; mf++) {
                uint32_t aa = abase +
                    (32 * wm + 16 * mf + (lane & 15)) * 144 +
                    ks * 32 + ((lane >> 4) << 4);
                ldmx4(ah[mf], aa);
                ldmx4(al[mf], aa + 73728);
            }
#pragma unroll
            for (int jj = 0; jj < 2; jj++) {
                uint32_t ba = bbase +
                    (32 * wn + 16 * jj + (lane & 7) + ((lane >> 4) << 3)) * 144 +
                    ks * 32 + (((lane >> 3) & 1) << 4);
                uint32_t bh[4], bl[4];
                ldmx4(bh, ba);
                ldmx4(bl, ba + 18432);
#pragma unroll
                for (int mf = 0; mf < 2; mf++) {
                    mma16816(c2[mf][2 * jj],     ah[mf], bh);
                    mma16816(c2[mf][2 * jj],     al[mf], bh);
                    mma16816(c2[mf][2 * jj],     ah[mf], bl);
                    mma16816(c2[mf][2 * jj + 1], ah[mf], bh + 2);
                    mma16816(c2[mf][2 * jj + 1], al[mf], bh + 2);
                    mma16816(c2[mf][2 * jj + 1], ah[mf], bl + 2);
                }
            }
        }
    }

    // L2 epilogue: h2 = relu(c2+b2) fp32 -> smem [128][132]
    __syncthreads();
    float* h2f = (float*)(smem + H2_F32);
#pragma unroll
    for (int mf = 0; mf < 2; mf++)
#pragma unroll
        for (int j = 0; j < 4; j++)
#pragma unroll
            for (int ci = 0; ci < 4; ci += 2) {
                int row = 32 * wm + 16 * mf + g + (ci ? 8 : 0);
                int col = 32 * wn + 8 * j + 2 * t4;
                h2f[row * 132 + col]     = fmaxf(c2[mf][j][ci]     + b2s[col],     0.f);
                h2f[row * 132 + col + 1] = fmaxf(c2[mf][j][ci + 1] + b2s[col + 1], 0.f);
            }
    __syncthreads();

    // ---------------- layer 3: [128,128] x [128,10], exact fp32 ------------
    for (int it = tid; it < 1280; it += NTHREADS) {
        int row = it / 10, col = it - row * 10;
        float acc = b3s[col];
        const float* hr = h2f + row * 132;
#pragma unroll 8
        for (int k = 0; k < 128; k++)
            acc = fmaf(hr[k], w3s[k * 10 + col], acc);
        out[((size_t)blockIdx.x * CTA_M + row) * 10 + col] = acc;
    }
}

// ---------------------------------------------------------------------------
extern "C" void kernel_launch(void* const* d_in, const int* in_sizes, int n_in,
                              void* d_out, int out_size) {
    const float* x  = (const float*)d_in[0];
    const float* cw = (const float*)d_in[1];
    const float* w1 = (const float*)d_in[2];
    const float* b1 = (const float*)d_in[3];
    const float* w2 = (const float*)d_in[4];
    const float* b2 = (const float*)d_in[5];
    const float* w3 = (const float*)d_in[6];
    const float* b3 = (const float*)d_in[7];
    (void)in_sizes; (void)n_in; (void)out_size;

    prep_w1T<<<832, 256>>>(cw, w1);
    prep_w2T<<<128, 256>>>(w2);

    static int cfg_done = 0;
    if (!cfg_done) {
        cudaFuncSetAttribute(fused_mlp,
                             cudaFuncAttributeMaxDynamicSharedMemorySize,
                             SMEM_SZ);
        cfg_done = 1;
    }
    fused_mlp<<<512, NTHREADS, SMEM_SZ>>>(x, b1, b2, b3, w3, (float*)d_out);
}

// round 12
// speedup vs baseline: 1.5004x; 1.5004x over previous
#include <cuda_runtime.h>
#include <cuda_fp16.h>
#include <stdint.h>

// ---------------------------------------------------------------------------
// out = relu(relu(conv3x3(x) @ w1 + b1) @ w2 + b2) @ w3 + b3 , B=65536
// conv folded into FC1 (W_eff). GEMMs via mma.sync m16n8k16 **fp16** with
// A-side hi/lo x2 split: a*b ~= (ah+al)*bh  (err ~1.4e-4 rms, B hi-only).
// Rationale: sm_103a legacy mma pipe measured at 0.25 HMMA/cyc/SM; kernel is
// at that roofline, so the only win is fewer HMMAs (bf16x3 -> f16x2 = -33%).
// ---------------------------------------------------------------------------

#define CTA_M    128
#define NTHREADS 512

// prep scratch: weight images, f16 hi only, chunk-major, 72-elem padded rows
__device__ __align__(16) __half g_w1hi[13 * 256 * 72];
__device__ __align__(16) __half g_w2hi[4 * 128 * 72];

// ---- smem layout (bytes, dynamic) ----
#define SM_B1   0                    // 256 f32
#define SM_B2   1024                 // 128 f32
#define SM_B3   1536                 // 16 f32
#define SM_W3   1600                 // 1280 f32
#define SM_MAIN 6720
// layer-1 phase: A hi/lo single buffer, B hi double buffer
#define L1A_HI  (SM_MAIN)            // [128][72] f16, stride 144 B
#define L1A_LO  (SM_MAIN + 18432)
#define L1B(b)  (SM_MAIN + 36864 + (b) * 36864)
// layer-2 phase (overlays dead L1 buffers)
#define H1_HI   (SM_MAIN)            // 4 chunks x [128][72] f16, chunk-major
#define H1_LO   (SM_MAIN + 73728)    // delta to H1_HI must stay 73728
#define L2B(b)  (SM_MAIN + 147456 + (b) * 18432)
// layer-3 phase
#define H2_F32  (SM_MAIN)            // [128][132] f32
#define SMEM_SZ 191040

// ---------------------------------------------------------------------------
__device__ __forceinline__ uint32_t s2u(const void* p) {
    uint32_t a;
    asm("{ .reg .u64 t; cvta.to.shared.u64 t, %1; cvt.u32.u64 %0, t; }"
        : "=r"(a) : "l"(p));
    return a;
}
__device__ __forceinline__ void ldmx4(uint32_t* r, uint32_t addr) {
    asm volatile("ldmatrix.sync.aligned.m8n8.x4.shared.b16 {%0,%1,%2,%3}, [%4];"
                 : "=r"(r[0]), "=r"(r[1]), "=r"(r[2]), "=r"(r[3]) : "r"(addr));
}
__device__ __forceinline__ void mma16816(float* c, const uint32_t* a,
                                         const uint32_t* b) {
    asm volatile(
        "mma.sync.aligned.m16n8k16.row.col.f32.f16.f16.f32 "
        "{%0,%1,%2,%3}, {%4,%5,%6,%7}, {%8,%9}, {%0,%1,%2,%3};"
        : "+f"(c[0]), "+f"(c[1]), "+f"(c[2]), "+f"(c[3])
        : "r"(a[0]), "r"(a[1]), "r"(a[2]), "r"(a[3]), "r"(b[0]), "r"(b[1]));
}
#define CP16(dst, src) \
    asm volatile("cp.async.cg.shared.global [%0], [%1], 16;" \
                 :: "r"(dst), "l"(src) : "memory")
#define CP_COMMIT() asm volatile("cp.async.commit_group;" ::: "memory")
#define CP_WAIT0()  asm volatile("cp.async.wait_group 0;" ::: "memory")

__device__ __forceinline__ uint32_t pkh(__half a, __half b) {
    unsigned short ra = *(unsigned short*)&a, rb = *(unsigned short*)&b;
    return (uint32_t)ra | ((uint32_t)rb << 16);
}
// split two f32 into packed f16-hi pair and f16-lo (residual) pair
__device__ __forceinline__ void split2h(float v0, float v1,
                                        uint32_t& hi, uint32_t& lo) {
    __half h0 = __float2half_rn(v0);
    __half h1 = __float2half_rn(v1);
    __half l0 = __float2half_rn(v0 - __half2float(h0));
    __half l1 = __float2half_rn(v1 - __half2float(h1));
    hi = pkh(h0, h1);
    lo = pkh(l0, l1);
}

// ---------------------------------------------------------------------------
// merged prep: W_eff^T (conv folded into w1) and w2^T, f16 hi, smem layout.
// 960 blocks x 256: idx < 212992 -> w1 element, else w2 element.
// (single prep launch => 2 launches/replay => ncu -s 5 captures fused_mlp)
// ---------------------------------------------------------------------------
__global__ void prep_weights(const float* __restrict__ cw,
                             const float* __restrict__ w1,
                             const float* __restrict__ w2) {
    int idx = blockIdx.x * 256 + threadIdx.x;
    if (idx < 212992) {                         // 256*832
        int n = idx / 832, p = idx % 832;
        float acc = 0.f;
        if (p < 784) {
            int r = p / 28, c = p % 28;
#pragma unroll
            for (int dr = 0; dr < 3; dr++)
#pragma unroll
                for (int dc = 0; dc < 3; dc++) {
                    int rr = r - dr, cc = c - dc;
                    if (rr >= 0 && rr < 26 && cc >= 0 && cc < 26)
                        acc += cw[dr * 3 + dc] * w1[(rr * 26 + cc) * 256 + n];
                }
        }
        int cc = p >> 6, kin = p & 63;
        g_w1hi[cc * 18432 + n * 72 + kin] = __float2half_rn(acc);
    } else {
        int i2 = idx - 212992;                  // 128*256
        int n = i2 / 256, k = i2 % 256;
        float v = w2[k * 128 + n];
        int ch = k >> 6, kin = k & 63;
        g_w2hi[ch * 9216 + n * 72 + kin] = __float2half_rn(v);
    }
}

// ---------------------------------------------------------------------------
// fused MLP: 1 CTA = 128 batch rows, 512 threads = 16 warps (4x4 warp grid)
// ---------------------------------------------------------------------------
__global__ void __launch_bounds__(NTHREADS, 1)
fused_mlp(const float* __restrict__ x, const float* __restrict__ b1g,
          const float* __restrict__ b2g, const float* __restrict__ b3g,
          const float* __restrict__ w3g, float* __restrict__ out) {
    extern __shared__ unsigned char smem[];
    const uint32_t sb = s2u(smem);
    const int tid = threadIdx.x;
    const int lane = tid & 31;
    const int wid = tid >> 5;
    const int wm = wid >> 2;
    const int wn = wid & 3;
    const int g = lane >> 2;
    const int t4 = lane & 3;

    float* b1s = (float*)(smem + SM_B1);
    float* b2s = (float*)(smem + SM_B2);
    float* b3s = (float*)(smem + SM_B3);
    float* w3s = (float*)(smem + SM_W3);
    for (int i = tid; i < 256; i += NTHREADS) b1s[i] = b1g[i];
    if (tid < 128) b2s[tid] = b2g[tid];
    if (tid < 16)  b3s[tid] = (tid < 10) ? b3g[tid] : 0.f;
    for (int i = tid; i < 1280; i += NTHREADS) w3s[i] = w3g[i];

    const float* xblk = x + (size_t)blockIdx.x * CTA_M * 784;

    // ---------------- layer 1: [128,832] x [832,256] -----------------------
    float c1[2][8][4];
#pragma unroll
    for (int a = 0; a < 2; a++)
#pragma unroll
        for (int b = 0; b < 8; b++)
#pragma unroll
            for (int c = 0; c < 4; c++) c1[a][b][c] = 0.f;

    // prologue: B chunk 0 via cp.async; A chunk 0 into regs
    {
        uint32_t dst = sb + L1B(0);
        const uint4* sh = (const uint4*)g_w1hi;
        for (int i = tid; i < 2304; i += NTHREADS) CP16(dst + i * 16, sh + i);
        CP_COMMIT();
    }
    float4 r[4];
#pragma unroll
    for (int j = 0; j < 4; j++) {
        int idx = tid + NTHREADS * j;
        int row = idx >> 4, f4 = idx & 15;
        r[j] = *(const float4*)(xblk + (size_t)row * 784 + f4 * 4);
    }

    for (int cc = 0; cc < 13; cc++) {
        CP_WAIT0();
        __syncthreads();   // B(cc) visible; MMA cc-1 fully done

        if (cc < 12) {     // issue B(cc+1) — overlaps STS + MMA below
            uint32_t dst = sb + L1B((cc + 1) & 1);
            const uint4* sh = (const uint4*)g_w1hi + (cc + 1) * 2304;
            for (int i = tid; i < 2304; i += NTHREADS) CP16(dst + i * 16, sh + i);
            CP_COMMIT();
        }
        // STS A(cc) from prefetched regs, f16 hi/lo split
#pragma unroll
        for (int j = 0; j < 4; j++) {
            int idx = tid + NTHREADS * j;
            int row = idx >> 4, f4 = idx & 15;
            uint32_t h0, l0, h1, l1;
            split2h(r[j].x, r[j].y, h0, l0);
            split2h(r[j].z, r[j].w, h1, l1);
            uint32_t off = row * 144 + f4 * 8;
            *(uint2*)(smem + L1A_HI + off) = make_uint2(h0, h1);
            *(uint2*)(smem + L1A_LO + off) = make_uint2(l0, l1);
        }
        if (cc < 12) {     // prefetch A(cc+1)
            int nc = cc + 1;
#pragma unroll
            for (int j = 0; j < 4; j++) {
                int idx = tid + NTHREADS * j;
                int row = idx >> 4, f4 = idx & 15;
                r[j] = make_float4(0.f, 0.f, 0.f, 0.f);
                if (nc < 12 || f4 < 4)
                    r[j] = *(const float4*)(xblk + (size_t)row * 784 + nc * 64 + f4 * 4);
            }
        }
        __syncthreads();   // A(cc) visible

        const uint32_t bbase = sb + L1B(cc & 1);
#pragma unroll
        for (int ks = 0; ks < 4; ks++) {
            uint32_t ah[2][4], al[2][4];
#pragma unroll
            for (int mf = 0; mf < 2; mf++) {
                uint32_t aa = sb + L1A_HI +
                    (32 * wm + 16 * mf + (lane & 15)) * 144 +
                    ks * 32 + ((lane >> 4) << 4);
                ldmx4(ah[mf], aa);
                ldmx4(al[mf], aa + 18432);
            }
#pragma unroll
            for (int jj = 0; jj < 4; jj++) {
                uint32_t ba = bbase +
                    (64 * wn + 16 * jj + (lane & 7) + ((lane >> 4) << 3)) * 144 +
                    ks * 32 + (((lane >> 3) & 1) << 4);
                uint32_t bh[4];
                ldmx4(bh, ba);
#pragma unroll
                for (int mf = 0; mf < 2; mf++) {
                    mma16816(c1[mf][2 * jj],     ah[mf], bh);
                    mma16816(c1[mf][2 * jj],     al[mf], bh);
                    mma16816(c1[mf][2 * jj + 1], ah[mf], bh + 2);
                    mma16816(c1[mf][2 * jj + 1], al[mf], bh + 2);
                }
            }
        }
    }

    // L1 epilogue: h1 = relu(c1+b1) -> H1 chunk-major f16 hi/lo
    __syncthreads();
#pragma unroll
    for (int mf = 0; mf < 2; mf++)
#pragma unroll
        for (int j = 0; j < 8; j++)
#pragma unroll
            for (int ci = 0; ci < 4; ci += 2) {
                int row = 32 * wm + 16 * mf + g + (ci ? 8 : 0);
                int col = 64 * wn + 8 * j + 2 * t4;
                float v0 = fmaxf(c1[mf][j][ci]     + b1s[col],     0.f);
                float v1 = fmaxf(c1[mf][j][ci + 1] + b1s[col + 1], 0.f);
                uint32_t hi, lo;
                split2h(v0, v1, hi, lo);
                uint32_t off = wn * 18432 + row * 144 + (8 * j + 2 * t4) * 2;
                *(uint32_t*)(smem + H1_HI + off) = hi;
                *(uint32_t*)(smem + H1_LO + off) = lo;
            }
    // issue w2 B chunk 0 (region disjoint from H1 and from L1 buffers)
    {
        uint32_t dst = sb + L2B(0);
        const uint4* sh = (const uint4*)g_w2hi;
        for (int i = tid; i < 1152; i += NTHREADS) CP16(dst + i * 16, sh + i);
        CP_COMMIT();
    }

    // ---------------- layer 2: [128,256] x [256,128] -----------------------
    float c2[2][4][4];
#pragma unroll
    for (int a = 0; a < 2; a++)
#pragma unroll
        for (int b = 0; b < 4; b++)
#pragma unroll
            for (int c = 0; c < 4; c++) c2[a][b][c] = 0.f;

    for (int ch = 0; ch < 4; ch++) {
        CP_WAIT0();
        __syncthreads();
        if (ch < 3) {
            uint32_t dst = sb + L2B((ch + 1) & 1);
            const uint4* sh = (const uint4*)g_w2hi + (ch + 1) * 1152;
            for (int i = tid; i < 1152; i += NTHREADS) CP16(dst + i * 16, sh + i);
            CP_COMMIT();
        }
        const uint32_t bbase = sb + L2B(ch & 1);
        const uint32_t abase = sb + H1_HI + ch * 18432;
#pragma unroll
        for (int ks = 0; ks < 4; ks++) {
            uint32_t ah[2][4], al[2][4];
#pragma unroll
            for (int mf = 0; mf < 2; mf++) {
                uint32_t aa = abase +
                    (32 * wm + 16 * mf + (lane & 15)) * 144 +
                    ks * 32 + ((lane >> 4) << 4);
                ldmx4(ah[mf], aa);
                ldmx4(al[mf], aa + 73728);
            }
#pragma unroll
            for (int jj = 0; jj < 2; jj++) {
                uint32_t ba = bbase +
                    (32 * wn + 16 * jj + (lane & 7) + ((lane >> 4) << 3)) * 144 +
                    ks * 32 + (((lane >> 3) & 1) << 4);
                uint32_t bh[4];
                ldmx4(bh, ba);
#pragma unroll
                for (int mf = 0; mf < 2; mf++) {
                    mma16816(c2[mf][2 * jj],     ah[mf], bh);
                    mma16816(c2[mf][2 * jj],     al[mf], bh);
                    mma16816(c2[mf][2 * jj + 1], ah[mf], bh + 2);
                    mma16816(c2[mf][2 * jj + 1], al[mf], bh + 2);
                }
            }
        }
    }

    // L2 epilogue: h2 = relu(c2+b2) fp32 -> smem [128][132]
    __syncthreads();
    float* h2f = (float*)(smem + H2_F32);
#pragma unroll
    for (int mf = 0; mf < 2; mf++)
#pragma unroll
        for (int j = 0; j < 4; j++)
#pragma unroll
            for (int ci = 0; ci < 4; ci += 2) {
                int row = 32 * wm + 16 * mf + g + (ci ? 8 : 0);
                int col = 32 * wn + 8 * j + 2 * t4;
                h2f[row * 132 + col]     = fmaxf(c2[mf][j][ci]     + b2s[col],     0.f);
                h2f[row * 132 + col + 1] = fmaxf(c2[mf][j][ci + 1] + b2s[col + 1], 0.f);
            }
    __syncthreads();

    // ---------------- layer 3: [128,128] x [128,10], exact fp32 ------------
    for (int it = tid; it < 1280; it += NTHREADS) {
        int row = it / 10, col = it - row * 10;
        float acc = b3s[col];
        const float* hr = h2f + row * 132;
#pragma unroll 8
        for (int k = 0; k < 128; k++)
            acc = fmaf(hr[k], w3s[k * 10 + col], acc);
        out[((size_t)blockIdx.x * CTA_M + row) * 10 + col] = acc;
    }
}

// ---------------------------------------------------------------------------
extern "C" void kernel_launch(void* const* d_in, const int* in_sizes, int n_in,
                              void* d_out, int out_size) {
    const float* x  = (const float*)d_in[0];
    const float* cw = (const float*)d_in[1];
    const float* w1 = (const float*)d_in[2];
    const float* b1 = (const float*)d_in[3];
    const float* w2 = (const float*)d_in[4];
    const float* b2 = (const float*)d_in[5];
    const float* w3 = (const float*)d_in[6];
    const float* b3 = (const float*)d_in[7];
    (void)in_sizes; (void)n_in; (void)out_size;

    prep_weights<<<960, 256>>>(cw, w1, w2);

    static int cfg_done = 0;
    if (!cfg_done) {
        cudaFuncSetAttribute(fused_mlp,
                             cudaFuncAttributeMaxDynamicSharedMemorySize,
                             SMEM_SZ);
        cfg_done = 1;
    }
    fused_mlp<<<512, NTHREADS, SMEM_SZ>>>(x, b1, b2, b3, w3, (float*)d_out);
}

// round 15
// speedup vs baseline: 1.8658x; 1.2435x over previous
#include <cuda_runtime.h>
#include <cuda_fp16.h>
#include <stdint.h>

// ---------------------------------------------------------------------------
// out = relu(relu(conv3x3(x) @ w1 + b1) @ w2 + b2) @ w3 + b3 , B=65536
// conv folded into FC1 (W_eff). GEMMs via mma.sync m16n8k16 fp16 with A-side
// hi/lo x2 split. This round: CTA_M=64 / 256 threads -> 98.9KB smem ->
// 2 CTAs/SM so staging/barriers of one CTA overlap MMA of the other
// (R12 ncu: tensor pipe only 47% active, 1 CTA/SM lockstep was the cap).
// ---------------------------------------------------------------------------

#define CTA_M    64
#define NTHREADS 256

// prep scratch: weight images, f16 hi only, chunk-major, 72-elem padded rows
__device__ __align__(16) __half g_w1hi[13 * 256 * 72];
__device__ __align__(16) __half g_w2hi[4 * 128 * 72];

// ---- smem layout (bytes, dynamic) ----
#define SM_B1   0                    // 256 f32
#define SM_B2   1024                 // 128 f32
#define SM_B3   1536                 // 16 f32
#define SM_W3   1600                 // 1280 f32
#define SM_MAIN 6720
// layer-1 phase: A hi/lo single buffer ([64][72] f16), B hi double buffer
#define L1A_HI  (SM_MAIN)            // 9216 B, stride 144 B
#define L1A_LO  (SM_MAIN + 9216)
#define L1B(b)  (SM_MAIN + 18432 + (b) * 36864)   // ends MAIN+92160
// layer-2 phase (overlays dead L1 buffers)
#define H1_HI   (SM_MAIN)            // 4 chunks x [64][72] f16, chunk-major
#define H1_LO   (SM_MAIN + 36864)    // delta 36864
#define L2B0    (SM_MAIN + 73728)    // single buffer, 18432 B
// layer-3 phase
#define H2_F32  (SM_MAIN)            // [64][132] f32
#define SMEM_SZ 98880

// ---------------------------------------------------------------------------
__device__ __forceinline__ uint32_t s2u(const void* p) {
    uint32_t a;
    asm("{ .reg .u64 t; cvta.to.shared.u64 t, %1; cvt.u32.u64 %0, t; }"
        : "=r"(a) : "l"(p));
    return a;
}
__device__ __forceinline__ void ldmx4(uint32_t* r, uint32_t addr) {
    asm volatile("ldmatrix.sync.aligned.m8n8.x4.shared.b16 {%0,%1,%2,%3}, [%4];"
                 : "=r"(r[0]), "=r"(r[1]), "=r"(r[2]), "=r"(r[3]) : "r"(addr));
}
__device__ __forceinline__ void mma16816(float* c, const uint32_t* a,
                                         const uint32_t* b) {
    asm volatile(
        "mma.sync.aligned.m16n8k16.row.col.f32.f16.f16.f32 "
        "{%0,%1,%2,%3}, {%4,%5,%6,%7}, {%8,%9}, {%0,%1,%2,%3};"
        : "+f"(c[0]), "+f"(c[1]), "+f"(c[2]), "+f"(c[3])
        : "r"(a[0]), "r"(a[1]), "r"(a[2]), "r"(a[3]), "r"(b[0]), "r"(b[1]));
}
#define CP16(dst, src) \
    asm volatile("cp.async.cg.shared.global [%0], [%1], 16;" \
                 :: "r"(dst), "l"(src) : "memory")
#define CP_COMMIT() asm volatile("cp.async.commit_group;" ::: "memory")
#define CP_WAIT0()  asm volatile("cp.async.wait_group 0;" ::: "memory")

__device__ __forceinline__ uint32_t pkh(__half a, __half b) {
    unsigned short ra = *(unsigned short*)&a, rb = *(unsigned short*)&b;
    return (uint32_t)ra | ((uint32_t)rb << 16);
}
__device__ __forceinline__ void split2h(float v0, float v1,
                                        uint32_t& hi, uint32_t& lo) {
    __half h0 = __float2half_rn(v0);
    __half h1 = __float2half_rn(v1);
    __half l0 = __float2half_rn(v0 - __half2float(h0));
    __half l1 = __float2half_rn(v1 - __half2float(h1));
    hi = pkh(h0, h1);
    lo = pkh(l0, l1);
}

// ---------------------------------------------------------------------------
// merged prep: W_eff^T (conv folded into w1) and w2^T, f16, smem-image layout
// ---------------------------------------------------------------------------
__global__ void prep_weights(const float* __restrict__ cw,
                             const float* __restrict__ w1,
                             const float* __restrict__ w2) {
    int idx = blockIdx.x * 256 + threadIdx.x;
    if (idx < 212992) {                         // 256*832
        int n = idx / 832, p = idx % 832;
        float acc = 0.f;
        if (p < 784) {
            int r = p / 28, c = p % 28;
#pragma unroll
            for (int dr = 0; dr < 3; dr++)
#pragma unroll
                for (int dc = 0; dc < 3; dc++) {
                    int rr = r - dr, cc = c - dc;
                    if (rr >= 0 && rr < 26 && cc >= 0 && cc < 26)
                        acc += cw[dr * 3 + dc] * w1[(rr * 26 + cc) * 256 + n];
                }
        }
        int cc = p >> 6, kin = p & 63;
        g_w1hi[cc * 18432 + n * 72 + kin] = __float2half_rn(acc);
    } else {
        int i2 = idx - 212992;                  // 128*256
        int n = i2 / 256, k = i2 % 256;
        float v = w2[k * 128 + n];
        int ch = k >> 6, kin = k & 63;
        g_w2hi[ch * 9216 + n * 72 + kin] = __float2half_rn(v);
    }
}

// ---------------------------------------------------------------------------
// fused MLP: 1 CTA = 64 batch rows, 256 threads = 8 warps (2x4 warp grid)
// ---------------------------------------------------------------------------
__global__ void __launch_bounds__(NTHREADS, 2)
fused_mlp(const float* __restrict__ x, const float* __restrict__ b1g,
          const float* __restrict__ b2g, const float* __restrict__ b3g,
          const float* __restrict__ w3g, float* __restrict__ out) {
    extern __shared__ unsigned char smem[];
    const uint32_t sb = s2u(smem);
    const int tid = threadIdx.x;
    const int lane = tid & 31;
    const int wid = tid >> 5;
    const int wm = wid >> 2;        // 0..1 -> rows 32*wm
    const int wn = wid & 3;         // 0..3 -> n-block 64*wn
    const int g = lane >> 2;
    const int t4 = lane & 3;

    float* b1s = (float*)(smem + SM_B1);
    float* b2s = (float*)(smem + SM_B2);
    float* b3s = (float*)(smem + SM_B3);
    float* w3s = (float*)(smem + SM_W3);
    for (int i = tid; i < 256; i += NTHREADS) b1s[i] = b1g[i];
    if (tid < 128) b2s[tid] = b2g[tid];
    if (tid < 16)  b3s[tid] = (tid < 10) ? b3g[tid] : 0.f;
    for (int i = tid; i < 1280; i += NTHREADS) w3s[i] = w3g[i];

    const float* xblk = x + (size_t)blockIdx.x * CTA_M * 784;

    // ---------------- layer 1: [64,832] x [832,256] ------------------------
    float c1[2][8][4];
#pragma unroll
    for (int a = 0; a < 2; a++)
#pragma unroll
        for (int b = 0; b < 8; b++)
#pragma unroll
            for (int c = 0; c < 4; c++) c1[a][b][c] = 0.f;

    // prologue: B chunk 0 via cp.async; A chunk 0 into regs
    {
        uint32_t dst = sb + L1B(0);
        const uint4* sh = (const uint4*)g_w1hi;
        for (int i = tid; i < 2304; i += NTHREADS) CP16(dst + i * 16, sh + i);
        CP_COMMIT();
    }
    float4 r[4];
#pragma unroll
    for (int j = 0; j < 4; j++) {
        int idx = tid + NTHREADS * j;            // 0..1023
        int row = idx >> 4, f4 = idx & 15;
        r[j] = *(const float4*)(xblk + (size_t)row * 784 + f4 * 4);
    }

    for (int cc = 0; cc < 13; cc++) {
        CP_WAIT0();
        __syncthreads();   // B(cc) visible; MMA cc-1 fully done

        if (cc < 12) {     // issue B(cc+1) — overlaps STS + MMA below
            uint32_t dst = sb + L1B((cc + 1) & 1);
            const uint4* sh = (const uint4*)g_w1hi + (cc + 1) * 2304;
            for (int i = tid; i < 2304; i += NTHREADS) CP16(dst + i * 16, sh + i);
            CP_COMMIT();
        }
        // STS A(cc) from prefetched regs, f16 hi/lo split
#pragma unroll
        for (int j = 0; j < 4; j++) {
            int idx = tid + NTHREADS * j;
            int row = idx >> 4, f4 = idx & 15;
            uint32_t h0, l0, h1, l1;
            split2h(r[j].x, r[j].y, h0, l0);
            split2h(r[j].z, r[j].w, h1, l1);
            uint32_t off = row * 144 + f4 * 8;
            *(uint2*)(smem + L1A_HI + off) = make_uint2(h0, h1);
            *(uint2*)(smem + L1A_LO + off) = make_uint2(l0, l1);
        }
        if (cc < 12) {     // prefetch A(cc+1)
            int nc = cc + 1;
#pragma unroll
            for (int j = 0; j < 4; j++) {
                int idx = tid + NTHREADS * j;
                int row = idx >> 4, f4 = idx & 15;
                r[j] = make_float4(0.f, 0.f, 0.f, 0.f);
                if (nc < 12 || f4 < 4)
                    r[j] = *(const float4*)(xblk + (size_t)row * 784 + nc * 64 + f4 * 4);
            }
        }
        __syncthreads();   // A(cc) visible

        const uint32_t bbase = sb + L1B(cc & 1);
#pragma unroll
        for (int ks = 0; ks < 4; ks++) {
            uint32_t ah[2][4], al[2][4];
#pragma unroll
            for (int mf = 0; mf < 2; mf++) {
                uint32_t aa = sb + L1A_HI +
                    (32 * wm + 16 * mf + (lane & 15)) * 144 +
                    ks * 32 + ((lane >> 4) << 4);
                ldmx4(ah[mf], aa);
                ldmx4(al[mf], aa + 9216);
            }
#pragma unroll
            for (int jj = 0; jj < 4; jj++) {
                uint32_t ba = bbase +
                    (64 * wn + 16 * jj + (lane & 7) + ((lane >> 4) << 3)) * 144 +
                    ks * 32 + (((lane >> 3) & 1) << 4);
                uint32_t bh[4];
                ldmx4(bh, ba);
                // hi pass (4 independent accs), then lo pass — spaces RAW chains
                mma16816(c1[0][2 * jj],     ah[0], bh);
                mma16816(c1[0][2 * jj + 1], ah[0], bh + 2);
                mma16816(c1[1][2 * jj],     ah[1], bh);
                mma16816(c1[1][2 * jj + 1], ah[1], bh + 2);
                mma16816(c1[0][2 * jj],     al[0], bh);
                mma16816(c1[0][2 * jj + 1], al[0], bh + 2);
                mma16816(c1[1][2 * jj],     al[1], bh);
                mma16816(c1[1][2 * jj + 1], al[1], bh + 2);
            }
        }
    }

    // L1 epilogue: h1 = relu(c1+b1) -> H1 chunk-major f16 hi/lo
    __syncthreads();
#pragma unroll
    for (int mf = 0; mf < 2; mf++)
#pragma unroll
        for (int j = 0; j < 8; j++)
#pragma unroll
            for (int ci = 0; ci < 4; ci += 2) {
                int row = 32 * wm + 16 * mf + g + (ci ? 8 : 0);
                int col = 64 * wn + 8 * j + 2 * t4;
                float v0 = fmaxf(c1[mf][j][ci]     + b1s[col],     0.f);
                float v1 = fmaxf(c1[mf][j][ci + 1] + b1s[col + 1], 0.f);
                uint32_t hi, lo;
                split2h(v0, v1, hi, lo);
                uint32_t off = wn * 9216 + row * 144 + (8 * j + 2 * t4) * 2;
                *(uint32_t*)(smem + H1_HI + off) = hi;
                *(uint32_t*)(smem + H1_LO + off) = lo;
            }
    // issue w2 B chunk 0 (region disjoint from H1 and L1 buffers)
    {
        uint32_t dst = sb + L2B0;
        const uint4* sh = (const uint4*)g_w2hi;
        for (int i = tid; i < 1152; i += NTHREADS) CP16(dst + i * 16, sh + i);
        CP_COMMIT();
    }

    // ---------------- layer 2: [64,256] x [256,128], single-buffer B -------
    float c2[2][4][4];
#pragma unroll
    for (int a = 0; a < 2; a++)
#pragma unroll
        for (int b = 0; b < 4; b++)
#pragma unroll
            for (int c = 0; c < 4; c++) c2[a][b][c] = 0.f;

    for (int ch = 0; ch < 4; ch++) {
        CP_WAIT0();
        __syncthreads();   // chunk ch staged (and H1 visible / prev MMA done)
        const uint32_t bbase = sb + L2B0;
        const uint32_t abase = sb + H1_HI + ch * 9216;
#pragma unroll
        for (int ks = 0; ks < 4; ks++) {
            uint32_t ah[2][4], al[2][4];
#pragma unroll
            for (int mf = 0; mf < 2; mf++) {
                uint32_t aa = abase +
                    (32 * wm + 16 * mf + (lane & 15)) * 144 +
                    ks * 32 + ((lane >> 4) << 4);
                ldmx4(ah[mf], aa);
                ldmx4(al[mf], aa + 36864);
            }
#pragma unroll
            for (int jj = 0; jj < 2; jj++) {
                uint32_t ba = bbase +
                    (32 * wn + 16 * jj + (lane & 7) + ((lane >> 4) << 3)) * 144 +
                    ks * 32 + (((lane >> 3) & 1) << 4);
                uint32_t bh[4];
                ldmx4(bh, ba);
                mma16816(c2[0][2 * jj],     ah[0], bh);
                mma16816(c2[0][2 * jj + 1], ah[0], bh + 2);
                mma16816(c2[1][2 * jj],     ah[1], bh);
                mma16816(c2[1][2 * jj + 1], ah[1], bh + 2);
                mma16816(c2[0][2 * jj],     al[0], bh);
                mma16816(c2[0][2 * jj + 1], al[0], bh + 2);
                mma16816(c2[1][2 * jj],     al[1], bh);
                mma16816(c2[1][2 * jj + 1], al[1], bh + 2);
            }
        }
        __syncthreads();   // MMA done, buffer free
        if (ch < 3) {
            uint32_t dst = sb + L2B0;
            const uint4* sh = (const uint4*)g_w2hi + (ch + 1) * 1152;
            for (int i = tid; i < 1152; i += NTHREADS) CP16(dst + i * 16, sh + i);
            CP_COMMIT();
        }
    }

    // L2 epilogue: h2 = relu(c2+b2) fp32 -> smem [64][132]
    __syncthreads();
    float* h2f = (float*)(smem + H2_F32);
#pragma unroll
    for (int mf = 0; mf < 2; mf++)
#pragma unroll
        for (int j = 0; j < 4; j++)
#pragma unroll
            for (int ci = 0; ci < 4; ci += 2) {
                int row = 32 * wm + 16 * mf + g + (ci ? 8 : 0);
                int col = 32 * wn + 8 * j + 2 * t4;
                h2f[row * 132 + col]     = fmaxf(c2[mf][j][ci]     + b2s[col],     0.f);
                h2f[row * 132 + col + 1] = fmaxf(c2[mf][j][ci + 1] + b2s[col + 1], 0.f);
            }
    __syncthreads();

    // ---------------- layer 3: [64,128] x [128,10], exact fp32 -------------
    for (int it = tid; it < 640; it += NTHREADS) {
        int row = it / 10, col = it - row * 10;
        float acc = b3s[col];
        const float* hr = h2f + row * 132;
#pragma unroll 8
        for (int k = 0; k < 128; k++)
            acc = fmaf(hr[k], w3s[k * 10 + col], acc);
        out[((size_t)blockIdx.x * CTA_M + row) * 10 + col] = acc;
    }
}

// ---------------------------------------------------------------------------
extern "C" void kernel_launch(void* const* d_in, const int* in_sizes, int n_in,
                              void* d_out, int out_size) {
    const float* x  = (const float*)d_in[0];
    const float* cw = (const float*)d_in[1];
    const float* w1 = (const float*)d_in[2];
    const float* b1 = (const float*)d_in[3];
    const float* w2 = (const float*)d_in[4];
    const float* b2 = (const float*)d_in[5];
    const float* w3 = (const float*)d_in[6];
    const float* b3 = (const float*)d_in[7];
    (void)in_sizes; (void)n_in; (void)out_size;

    prep_weights<<<960, 256>>>(cw, w1, w2);

    static int cfg_done = 0;
    if (!cfg_done) {
        cudaFuncSetAttribute(fused_mlp,
                             cudaFuncAttributeMaxDynamicSharedMemorySize,
                             SMEM_SZ);
        cfg_done = 1;
    }
    fused_mlp<<<1024, NTHREADS, SMEM_SZ>>>(x, b1, b2, b3, w3, (float*)d_out);
}

// round 16
// speedup vs baseline: 2.7004x; 1.4473x over previous
#include <cuda_runtime.h>
#include <cuda_fp16.h>
#include <stdint.h>

// ---------------------------------------------------------------------------
// out = relu(relu(conv3x3(x) @ w1 + b1) @ w2 + b2) @ w3 + b3 , B=65536
// conv folded into FC1 (W_eff). GEMMs via mma.sync m16n8k16 fp16, SINGLE pass
// (plain f16 A and W). Error model: W-rounding gave 2.8e-4 measured; adding
// independent A/h1 rounding => ~sqrt(2)*2.8e-4 ~ 4e-4 < 1e-3 gate. Halves
// HMMA count vs R15 (tensor pipe was the roofline at 58.8% active).
// 2 CTAs/SM (89.7KB smem, 256 thr) so one CTA's staging hides the other's MMA.
// ---------------------------------------------------------------------------

#define CTA_M    64
#define NTHREADS 256

// prep scratch: weight images, f16, chunk-major, 72-elem padded rows
__device__ __align__(16) __half g_w1hi[13 * 256 * 72];
__device__ __align__(16) __half g_w2hi[4 * 128 * 72];

// ---- smem layout (bytes, dynamic) ----
#define SM_B1   0                    // 256 f32
#define SM_B2   1024                 // 128 f32
#define SM_B3   1536                 // 16 f32
#define SM_W3   1600                 // 1280 f32
#define SM_MAIN 6720
// layer-1 phase: A single buffer ([64][72] f16), B double buffer
#define L1A_HI  (SM_MAIN)            // 9216 B, stride 144 B
#define L1B(b)  (SM_MAIN + 9216 + (b) * 36864)    // ends MAIN+82944
// layer-2 phase (overlays dead L1 buffers)
#define H1_HI   (SM_MAIN)            // 4 chunks x [64][72] f16, chunk-major
#define L2B0    (SM_MAIN + 36864)    // single buffer, 18432 B
// layer-3 phase
#define H2_F32  (SM_MAIN)            // [64][132] f32
#define SMEM_SZ 89664

// ---------------------------------------------------------------------------
__device__ __forceinline__ uint32_t s2u(const void* p) {
    uint32_t a;
    asm("{ .reg .u64 t; cvta.to.shared.u64 t, %1; cvt.u32.u64 %0, t; }"
        : "=r"(a) : "l"(p));
    return a;
}
__device__ __forceinline__ void ldmx4(uint32_t* r, uint32_t addr) {
    asm volatile("ldmatrix.sync.aligned.m8n8.x4.shared.b16 {%0,%1,%2,%3}, [%4];"
                 : "=r"(r[0]), "=r"(r[1]), "=r"(r[2]), "=r"(r[3]) : "r"(addr));
}
__device__ __forceinline__ void mma16816(float* c, const uint32_t* a,
                                         const uint32_t* b) {
    asm volatile(
        "mma.sync.aligned.m16n8k16.row.col.f32.f16.f16.f32 "
        "{%0,%1,%2,%3}, {%4,%5,%6,%7}, {%8,%9}, {%0,%1,%2,%3};"
        : "+f"(c[0]), "+f"(c[1]), "+f"(c[2]), "+f"(c[3])
        : "r"(a[0]), "r"(a[1]), "r"(a[2]), "r"(a[3]), "r"(b[0]), "r"(b[1]));
}
#define CP16(dst, src) \
    asm volatile("cp.async.cg.shared.global [%0], [%1], 16;" \
                 :: "r"(dst), "l"(src) : "memory")
#define CP_COMMIT() asm volatile("cp.async.commit_group;" ::: "memory")
#define CP_WAIT0()  asm volatile("cp.async.wait_group 0;" ::: "memory")

__device__ __forceinline__ uint32_t h2u(__half2 h) {
    return *(uint32_t*)&h;
}

// ---------------------------------------------------------------------------
// merged prep: W_eff^T (conv folded into w1) and w2^T, f16, smem-image layout
// ---------------------------------------------------------------------------
__global__ void prep_weights(const float* __restrict__ cw,
                             const float* __restrict__ w1,
                             const float* __restrict__ w2) {
    int idx = blockIdx.x * 256 + threadIdx.x;
    if (idx < 212992) {                         // 256*832
        int n = idx / 832, p = idx % 832;
        float acc = 0.f;
        if (p < 784) {
            int r = p / 28, c = p % 28;
#pragma unroll
            for (int dr = 0; dr < 3; dr++)
#pragma unroll
                for (int dc = 0; dc < 3; dc++) {
                    int rr = r - dr, cc = c - dc;
                    if (rr >= 0 && rr < 26 && cc >= 0 && cc < 26)
                        acc += cw[dr * 3 + dc] * w1[(rr * 26 + cc) * 256 + n];
                }
        }
        int cc = p >> 6, kin = p & 63;
        g_w1hi[cc * 18432 + n * 72 + kin] = __float2half_rn(acc);
    } else {
        int i2 = idx - 212992;                  // 128*256
        int n = i2 / 256, k = i2 % 256;
        float v = w2[k * 128 + n];
        int ch = k >> 6, kin = k & 63;
        g_w2hi[ch * 9216 + n * 72 + kin] = __float2half_rn(v);
    }
}

// ---------------------------------------------------------------------------
// fused MLP: 1 CTA = 64 batch rows, 256 threads = 8 warps (2x4 warp grid)
// ---------------------------------------------------------------------------
__global__ void __launch_bounds__(NTHREADS, 2)
fused_mlp(const float* __restrict__ x, const float* __restrict__ b1g,
          const float* __restrict__ b2g, const float* __restrict__ b3g,
          const float* __restrict__ w3g, float* __restrict__ out) {
    extern __shared__ unsigned char smem[];
    const uint32_t sb = s2u(smem);
    const int tid = threadIdx.x;
    const int lane = tid & 31;
    const int wid = tid >> 5;
    const int wm = wid >> 2;        // 0..1 -> rows 32*wm
    const int wn = wid & 3;         // 0..3 -> n-block 64*wn
    const int g = lane >> 2;
    const int t4 = lane & 3;

    float* b1s = (float*)(smem + SM_B1);
    float* b2s = (float*)(smem + SM_B2);
    float* b3s = (float*)(smem + SM_B3);
    float* w3s = (float*)(smem + SM_W3);
    for (int i = tid; i < 256; i += NTHREADS) b1s[i] = b1g[i];
    if (tid < 128) b2s[tid] = b2g[tid];
    if (tid < 16)  b3s[tid] = (tid < 10) ? b3g[tid] : 0.f;
    for (int i = tid; i < 1280; i += NTHREADS) w3s[i] = w3g[i];

    const float* xblk = x + (size_t)blockIdx.x * CTA_M * 784;

    // ---------------- layer 1: [64,832] x [832,256] ------------------------
    float c1[2][8][4];
#pragma unroll
    for (int a = 0; a < 2; a++)
#pragma unroll
        for (int b = 0; b < 8; b++)
#pragma unroll
            for (int c = 0; c < 4; c++) c1[a][b][c] = 0.f;

    // prologue: B chunk 0 via cp.async; A chunk 0 into regs
    {
        uint32_t dst = sb + L1B(0);
        const uint4* sh = (const uint4*)g_w1hi;
        for (int i = tid; i < 2304; i += NTHREADS) CP16(dst + i * 16, sh + i);
        CP_COMMIT();
    }
    float4 r[4];
#pragma unroll
    for (int j = 0; j < 4; j++) {
        int idx = tid + NTHREADS * j;            // 0..1023
        int row = idx >> 4, f4 = idx & 15;
        r[j] = *(const float4*)(xblk + (size_t)row * 784 + f4 * 4);
    }

    for (int cc = 0; cc < 13; cc++) {
        CP_WAIT0();
        __syncthreads();   // B(cc) visible; MMA cc-1 fully done

        if (cc < 12) {     // issue B(cc+1) — overlaps STS + MMA below
            uint32_t dst = sb + L1B((cc + 1) & 1);
            const uint4* sh = (const uint4*)g_w1hi + (cc + 1) * 2304;
            for (int i = tid; i < 2304; i += NTHREADS) CP16(dst + i * 16, sh + i);
            CP_COMMIT();
        }
        // STS A(cc) from prefetched regs, plain f16
#pragma unroll
        for (int j = 0; j < 4; j++) {
            int idx = tid + NTHREADS * j;
            int row = idx >> 4, f4 = idx & 15;
            uint32_t h0 = h2u(__float22half2_rn(make_float2(r[j].x, r[j].y)));
            uint32_t h1 = h2u(__float22half2_rn(make_float2(r[j].z, r[j].w)));
            *(uint2*)(smem + L1A_HI + row * 144 + f4 * 8) = make_uint2(h0, h1);
        }
        if (cc < 12) {     // prefetch A(cc+1)
            int nc = cc + 1;
#pragma unroll
            for (int j = 0; j < 4; j++) {
                int idx = tid + NTHREADS * j;
                int row = idx >> 4, f4 = idx & 15;
                r[j] = make_float4(0.f, 0.f, 0.f, 0.f);
                if (nc < 12 || f4 < 4)
                    r[j] = *(const float4*)(xblk + (size_t)row * 784 + nc * 64 + f4 * 4);
            }
        }
        __syncthreads();   // A(cc) visible

        const uint32_t bbase = sb + L1B(cc & 1);
#pragma unroll
        for (int ks = 0; ks < 4; ks++) {
            uint32_t ah[2][4];
#pragma unroll
            for (int mf = 0; mf < 2; mf++) {
                uint32_t aa = sb + L1A_HI +
                    (32 * wm + 16 * mf + (lane & 15)) * 144 +
                    ks * 32 + ((lane >> 4) << 4);
                ldmx4(ah[mf], aa);
            }
#pragma unroll
            for (int jj = 0; jj < 4; jj++) {
                uint32_t ba = bbase +
                    (64 * wn + 16 * jj + (lane & 7) + ((lane >> 4) << 3)) * 144 +
                    ks * 32 + (((lane >> 3) & 1) << 4);
                uint32_t bh[4];
                ldmx4(bh, ba);
                // 4 independent accumulators — no RAW chaining
                mma16816(c1[0][2 * jj],     ah[0], bh);
                mma16816(c1[0][2 * jj + 1], ah[0], bh + 2);
                mma16816(c1[1][2 * jj],     ah[1], bh);
                mma16816(c1[1][2 * jj + 1], ah[1], bh + 2);
            }
        }
    }

    // L1 epilogue: h1 = relu(c1+b1) -> H1 chunk-major f16
    __syncthreads();
#pragma unroll
    for (int mf = 0; mf < 2; mf++)
#pragma unroll
        for (int j = 0; j < 8; j++)
#pragma unroll
            for (int ci = 0; ci < 4; ci += 2) {
                int row = 32 * wm + 16 * mf + g + (ci ? 8 : 0);
                int col = 64 * wn + 8 * j + 2 * t4;
                float v0 = fmaxf(c1[mf][j][ci]     + b1s[col],     0.f);
                float v1 = fmaxf(c1[mf][j][ci + 1] + b1s[col + 1], 0.f);
                uint32_t hi = h2u(__float22half2_rn(make_float2(v0, v1)));
                uint32_t off = wn * 9216 + row * 144 + (8 * j + 2 * t4) * 2;
                *(uint32_t*)(smem + H1_HI + off) = hi;
            }
    // issue w2 B chunk 0 (region disjoint from H1 and L1 buffers)
    {
        uint32_t dst = sb + L2B0;
        const uint4* sh = (const uint4*)g_w2hi;
        for (int i = tid; i < 1152; i += NTHREADS) CP16(dst + i * 16, sh + i);
        CP_COMMIT();
    }

    // ---------------- layer 2: [64,256] x [256,128], single-buffer B -------
    float c2[2][4][4];
#pragma unroll
    for (int a = 0; a < 2; a++)
#pragma unroll
        for (int b = 0; b < 4; b++)
#pragma unroll
            for (int c = 0; c < 4; c++) c2[a][b][c] = 0.f;

    for (int ch = 0; ch < 4; ch++) {
        CP_WAIT0();
        __syncthreads();   // chunk ch staged (H1 visible / prev MMA done)
        const uint32_t bbase = sb + L2B0;
        const uint32_t abase = sb + H1_HI + ch * 9216;
#pragma unroll
        for (int ks = 0; ks < 4; ks++) {
            uint32_t ah[2][4];
#pragma unroll
            for (int mf = 0; mf < 2; mf++) {
                uint32_t aa = abase +
                    (32 * wm + 16 * mf + (lane & 15)) * 144 +
                    ks * 32 + ((lane >> 4) << 4);
                ldmx4(ah[mf], aa);
            }
#pragma unroll
            for (int jj = 0; jj < 2; jj++) {
                uint32_t ba = bbase +
                    (32 * wn + 16 * jj + (lane & 7) + ((lane >> 4) << 3)) * 144 +
                    ks * 32 + (((lane >> 3) & 1) << 4);
                uint32_t bh[4];
                ldmx4(bh, ba);
                mma16816(c2[0][2 * jj],     ah[0], bh);
                mma16816(c2[0][2 * jj + 1], ah[0], bh + 2);
                mma16816(c2[1][2 * jj],     ah[1], bh);
                mma16816(c2[1][2 * jj + 1], ah[1], bh + 2);
            }
        }
        __syncthreads();   // MMA done, buffer free
        if (ch < 3) {
            uint32_t dst = sb + L2B0;
            const uint4* sh = (const uint4*)g_w2hi + (ch + 1) * 1152;
            for (int i = tid; i < 1152; i += NTHREADS) CP16(dst + i * 16, sh + i);
            CP_COMMIT();
        }
    }

    // L2 epilogue: h2 = relu(c2+b2) fp32 -> smem [64][132]
    __syncthreads();
    float* h2f = (float*)(smem + H2_F32);
#pragma unroll
    for (int mf = 0; mf < 2; mf++)
#pragma unroll
        for (int j = 0; j < 4; j++)
#pragma unroll
            for (int ci = 0; ci < 4; ci += 2) {
                int row = 32 * wm + 16 * mf + g + (ci ? 8 : 0);
                int col = 32 * wn + 8 * j + 2 * t4;
                h2f[row * 132 + col]     = fmaxf(c2[mf][j][ci]     + b2s[col],     0.f);
                h2f[row * 132 + col + 1] = fmaxf(c2[mf][j][ci + 1] + b2s[col + 1], 0.f);
            }
    __syncthreads();

    // ---------------- layer 3: [64,128] x [128,10], exact fp32 -------------
    for (int it = tid; it < 640; it += NTHREADS) {
        int row = it / 10, col = it - row * 10;
        float acc = b3s[col];
        const float* hr = h2f + row * 132;
#pragma unroll 8
        for (int k = 0; k < 128; k++)
            acc = fmaf(hr[k], w3s[k * 10 + col], acc);
        out[((size_t)blockIdx.x * CTA_M + row) * 10 + col] = acc;
    }
}

// ---------------------------------------------------------------------------
extern "C" void kernel_launch(void* const* d_in, const int* in_sizes, int n_in,
                              void* d_out, int out_size) {
    const float* x  = (const float*)d_in[0];
    const float* cw = (const float*)d_in[1];
    const float* w1 = (const float*)d_in[2];
    const float* b1 = (const float*)d_in[3];
    const float* w2 = (const float*)d_in[4];
    const float* b2 = (const float*)d_in[5];
    const float* w3 = (const float*)d_in[6];
    const float* b3 = (const float*)d_in[7];
    (void)in_sizes; (void)n_in; (void)out_size;

    prep_weights<<<960, 256>>>(cw, w1, w2);

    static int cfg_done = 0;
    if (!cfg_done) {
        cudaFuncSetAttribute(fused_mlp,
                             cudaFuncAttributeMaxDynamicSharedMemorySize,
                             SMEM_SZ);
        cfg_done = 1;
    }
    fused_mlp<<<1024, NTHREADS, SMEM_SZ>>>(x, b1, b2, b3, w3, (float*)d_out);
}